// round 10
// baseline (speedup 1.0000x reference)
#include <cuda_runtime.h>
#include <cuda_bf16.h>
#include <math.h>
#include <float.h>
#include <stdint.h>

// Problem constants
#define NB 2
#define NS 2048
#define ND 2048
#define NH 16
#define HD 128
#define NM (NB*NS)          // 4096 rows for GEMMs
#define K2 (3*ND)           // 6144: split-bf16 K concat [hi|lo|hi] x [hi|hi|lo]
#define NEG_BIG (-3.402823466e38f)

// Scratch (allocations are banned -> device globals)
__device__ float g_q[NB*NH*NS*HD];          // [b][h][s][d]
__device__ float g_k[NB*NH*NS*HD];
__device__ float g_v[NB*NH*NS*HD];
__device__ float g_o[NB*NS*ND];             // [b][s][h*hd+d]
__device__ float g_cos[NS*(HD/2)];
__device__ float g_sin[NS*(HD/2)];
__device__ __nv_bfloat16 gx2 [NM*K2];       // split(x)   [hi|lo|hi]
__device__ __nv_bfloat16 go2 [NM*K2];       // split(g_o) [hi|lo|hi]
__device__ __nv_bfloat16 gwq2[ND*K2];       // split(w)   [hi|hi|lo]
__device__ __nv_bfloat16 gwk2[ND*K2];
__device__ __nv_bfloat16 gwv2[ND*K2];
__device__ __nv_bfloat16 gwo2[ND*K2];

// ---------------------------------------------------------------------------
// RoPE tables (reference strided-slice semantics):
//   inv_freq[j] = base^{-(2j)/128}, j in [0,64)
//   cos_tab[s][i] = cos(s * inv_freq[(2i)   mod 64])
//   sin_tab[s][i] = sin(s * inv_freq[(2i+1) mod 64])
// ---------------------------------------------------------------------------
__global__ void rope_init_kernel() {
    int s = blockIdx.x;
    int i = threadIdx.x;            // 0..63
    int fc = (2*i) & 63;
    int fs = (2*i + 1) & 63;
    double invc = pow(10000.0, -(double)(2*fc) / 128.0);
    double invs = pow(10000.0, -(double)(2*fs) / 128.0);
    g_cos[s*64 + i] = (float)cos((double)s * invc);
    g_sin[s*64 + i] = (float)sin((double)s * invs);
}

// ---------------------------------------------------------------------------
// fp32 -> split bf16 (hi+lo). PAT 0 ("A" side): segments [hi, lo, hi].
//                             PAT 1 ("B" side): segments [hi, hi, lo].
// src is row-major [rows][2048]; dst [rows][6144]. Grid covers rows*2048.
// ---------------------------------------------------------------------------
template<int PAT>
__global__ void conv_split(const float* __restrict__ src,
                           __nv_bfloat16* __restrict__ dst) {
    int idx = blockIdx.x * 256 + threadIdx.x;
    float v = src[idx];
    __nv_bfloat16 hi = __float2bfloat16(v);
    __nv_bfloat16 lo = __float2bfloat16(v - __bfloat162float(hi));
    int row = idx >> 11;
    int k   = idx & 2047;
    size_t base = (size_t)row * K2 + k;
    if (PAT == 0) {
        dst[base]          = hi;
        dst[base + ND]     = lo;
        dst[base + 2*ND]   = hi;
    } else {
        dst[base]          = hi;
        dst[base + ND]     = hi;
        dst[base + 2*ND]   = lo;
    }
}

// ---------------------------------------------------------------------------
// mma.sync m16n8k16 row.col bf16 -> f32
// ---------------------------------------------------------------------------
__device__ __forceinline__ void mma_bf16(float* c, const uint32_t* a, const uint32_t* b) {
    asm volatile(
        "mma.sync.aligned.m16n8k16.row.col.f32.bf16.bf16.f32 "
        "{%0,%1,%2,%3}, {%4,%5,%6,%7}, {%8,%9}, {%0,%1,%2,%3};\n"
        : "+f"(c[0]), "+f"(c[1]), "+f"(c[2]), "+f"(c[3])
        : "r"(a[0]), "r"(a[1]), "r"(a[2]), "r"(a[3]), "r"(b[0]), "r"(b[1]));
}

// ---------------------------------------------------------------------------
// NT bf16 GEMM (tensor cores): C[m][n] = sum_k A2[m][k]*B2[n][k], K2=6144.
// Block 128x128, 256 threads = 8 warps (2x4), warp tile 64x32.
// Per warp: 4 m-frags (16) x 4 n-frags (8). Fragments loaded with plain LDS
// (documented mma.sync layouts; no ldmatrix). Smem row stride 40 halves ->
// conflict-free fragment loads. Double-buffered k-tile of 32.
// MODE 0: -> g_q (RoPE)  1: -> g_k (RoPE)  2: -> g_v (head layout)
// MODE 3: -> outp row-major
// ---------------------------------------------------------------------------
template<int MODE>
__global__ __launch_bounds__(256) void hgemm_nt(const __nv_bfloat16* __restrict__ A2,
                                                const __nv_bfloat16* __restrict__ B2,
                                                float* __restrict__ outp) {
    __shared__ __nv_bfloat16 As[2][128*40];
    __shared__ __nv_bfloat16 Bs[2][128*40];
    const int t    = threadIdx.x;
    const int warp = t >> 5;
    const int lane = t & 31;
    const int g    = lane >> 2;         // groupID (0..7)
    const int tg   = lane & 3;          // thread-in-group (0..3)
    const int wm   = (warp >> 2) * 64;  // warp m offset (0/64)
    const int wn   = (warp & 3) * 32;   // warp n offset (0/32/64/96)
    const int m0   = blockIdx.y * 128;
    const int n0   = blockIdx.x * 128;

    float c[4][4][4];
#pragma unroll
    for (int mf = 0; mf < 4; mf++)
#pragma unroll
        for (int nf = 0; nf < 4; nf++)
#pragma unroll
            for (int r = 0; r < 4; r++) c[mf][nf][r] = 0.f;

    // Global->smem loaders: thread t fills row (t>>1), 16 halves at (t&1)*16.
    const int lr = t >> 1;
    const int lc = (t & 1) * 16;
    const __nv_bfloat16* Ap = A2 + (size_t)(m0 + lr) * K2 + lc;
    const __nv_bfloat16* Bp = B2 + (size_t)(n0 + lr) * K2 + lc;

    // Prologue: k-tile 0
    {
        uint4 a0 = *(const uint4*)(Ap);
        uint4 a1 = *(const uint4*)(Ap + 8);
        uint4 b0 = *(const uint4*)(Bp);
        uint4 b1 = *(const uint4*)(Bp + 8);
        *(uint4*)&As[0][lr*40 + lc]     = a0;
        *(uint4*)&As[0][lr*40 + lc + 8] = a1;
        *(uint4*)&Bs[0][lr*40 + lc]     = b0;
        *(uint4*)&Bs[0][lr*40 + lc + 8] = b1;
    }
    __syncthreads();

    int buf = 0;
    for (int k0 = 0; k0 < K2; k0 += 32) {
        uint4 na0, na1, nb0, nb1;
        const bool has_next = (k0 + 32) < K2;
        if (has_next) {
            na0 = *(const uint4*)(Ap + k0 + 32);
            na1 = *(const uint4*)(Ap + k0 + 40);
            nb0 = *(const uint4*)(Bp + k0 + 32);
            nb1 = *(const uint4*)(Bp + k0 + 40);
        }
        const __nv_bfloat16* Asb = &As[buf][0];
        const __nv_bfloat16* Bsb = &Bs[buf][0];
#pragma unroll
        for (int ks = 0; ks < 2; ks++) {
            uint32_t af[4][4];
#pragma unroll
            for (int mf = 0; mf < 4; mf++) {
                int r0 = (wm + mf*16 + g)*40 + ks*16 + tg*2;
                af[mf][0] = *(const uint32_t*)&Asb[r0];            // (g    , k0-7)
                af[mf][1] = *(const uint32_t*)&Asb[r0 + 8*40];     // (g+8  , k0-7)
                af[mf][2] = *(const uint32_t*)&Asb[r0 + 8];        // (g    , k8-15)
                af[mf][3] = *(const uint32_t*)&Asb[r0 + 8*40 + 8]; // (g+8  , k8-15)
            }
            uint32_t bfr[4][2];
#pragma unroll
            for (int nf = 0; nf < 4; nf++) {
                int r0 = (wn + nf*8 + g)*40 + ks*16 + tg*2;
                bfr[nf][0] = *(const uint32_t*)&Bsb[r0];           // (k=tg*2  , n=g)
                bfr[nf][1] = *(const uint32_t*)&Bsb[r0 + 8];       // (k=tg*2+8, n=g)
            }
#pragma unroll
            for (int mf = 0; mf < 4; mf++)
#pragma unroll
                for (int nf = 0; nf < 4; nf++)
                    mma_bf16(c[mf][nf], af[mf], bfr[nf]);
        }
        if (has_next) {
            int nb = buf ^ 1;
            *(uint4*)&As[nb][lr*40 + lc]     = na0;
            *(uint4*)&As[nb][lr*40 + lc + 8] = na1;
            *(uint4*)&Bs[nb][lr*40 + lc]     = nb0;
            *(uint4*)&Bs[nb][lr*40 + lc + 8] = nb1;
            __syncthreads();
            buf = nb;
        }
    }

    // Epilogue. Element map: frag (mf,nf) reg r -> row m0+wm+mf*16+g+(r>=2)*8,
    // col n0+wn+nf*8+tg*2+(r&1). Col pairs (even,odd) are intra-thread.
#pragma unroll
    for (int mf = 0; mf < 4; mf++) {
#pragma unroll
        for (int nf = 0; nf < 4; nf++) {
            int col = n0 + wn + nf*8 + tg*2;
#pragma unroll
            for (int rp = 0; rp < 2; rp++) {
                int row = m0 + wm + mf*16 + g + rp*8;
                float ve = c[mf][nf][rp*2];
                float vo = c[mf][nf][rp*2 + 1];
                int bb = row >> 11;
                int ss = row & 2047;
                if (MODE == 3) {
                    float2 p; p.x = ve; p.y = vo;
                    *(float2*)&outp[(size_t)row * ND + col] = p;
                } else if (MODE == 2) {
                    int h = col >> 7, d = col & 127;
                    size_t base = (((size_t)(bb*NH + h))*NS + ss)*HD + d;
                    g_v[base]     = ve;
                    g_v[base + 1] = vo;
                } else {
                    float* dst = (MODE == 0) ? g_q : g_k;
                    int h = col >> 7, d = col & 127;
                    int ip = d >> 1;
                    float cc = g_cos[ss*64 + ip];
                    float sn = g_sin[ss*64 + ip];
                    size_t base = (((size_t)(bb*NH + h))*NS + ss)*HD + d;
                    dst[base]     = ve*cc - vo*sn;
                    dst[base + 1] = ve*sn + vo*cc;
                }
            }
        }
    }
}

// ---------------------------------------------------------------------------
// Flash attention, fp32, causal. One block per (q-tile of 64, b*h).
// Br=Bc=64, hd=128. Online softmax. 256 threads (16x16).
// ---------------------------------------------------------------------------
__global__ __launch_bounds__(256) void flash_attn() {
    extern __shared__ float sm[];
    float* Qt = sm;                  // [128][64]
    float* Kt = Qt + 128*64;         // [128][64]
    float* Vs = Kt + 128*64;         // [64][128]
    float* Ps = Vs + 64*128;         // [64][68]

    const int t  = threadIdx.x;
    const int tx = t & 15;
    const int ty = t >> 4;
    const int qi = blockIdx.x;
    const int bh = blockIdx.y;
    const int q0 = qi * 64;
    const float scale = 0.08838834764831845f;   // 1/sqrt(128)

    const float* Qg = g_q + (size_t)bh * NS * HD;
    const float* Kg = g_k + (size_t)bh * NS * HD;
    const float* Vg = g_v + (size_t)bh * NS * HD;

    for (int idx = t; idx < 64*32; idx += 256) {
        int r = idx >> 5;
        int c = (idx & 31) << 2;
        float4 v = *(const float4*)(Qg + (size_t)(q0 + r)*HD + c);
        Qt[(c+0)*64 + r] = v.x * scale;
        Qt[(c+1)*64 + r] = v.y * scale;
        Qt[(c+2)*64 + r] = v.z * scale;
        Qt[(c+3)*64 + r] = v.w * scale;
    }

    float m_i[4], l_i[4], acc[4][8];
#pragma unroll
    for (int i = 0; i < 4; i++) {
        m_i[i] = NEG_BIG;
        l_i[i] = 0.f;
#pragma unroll
        for (int j = 0; j < 8; j++) acc[i][j] = 0.f;
    }

    const int ntiles = qi + 1;
    for (int kt = 0; kt < ntiles; kt++) {
        int k0 = kt * 64;
        __syncthreads();
        for (int idx = t; idx < 64*32; idx += 256) {
            int r = idx >> 5;
            int c = (idx & 31) << 2;
            float4 kv = *(const float4*)(Kg + (size_t)(k0 + r)*HD + c);
            Kt[(c+0)*64 + r] = kv.x;
            Kt[(c+1)*64 + r] = kv.y;
            Kt[(c+2)*64 + r] = kv.z;
            Kt[(c+3)*64 + r] = kv.w;
            float4 vv = *(const float4*)(Vg + (size_t)(k0 + r)*HD + c);
            *(float4*)&Vs[r*128 + c] = vv;
        }
        __syncthreads();

        float sreg[4][4];
#pragma unroll
        for (int i = 0; i < 4; i++)
#pragma unroll
            for (int j = 0; j < 4; j++) sreg[i][j] = 0.f;

        for (int d = 0; d < 128; d++) {
            float4 qa = *(const float4*)&Qt[d*64 + ty*4];
            float4 kb = *(const float4*)&Kt[d*64 + tx*4];
            float a[4] = {qa.x, qa.y, qa.z, qa.w};
            float b[4] = {kb.x, kb.y, kb.z, kb.w};
#pragma unroll
            for (int i = 0; i < 4; i++)
#pragma unroll
                for (int j = 0; j < 4; j++)
                    sreg[i][j] = fmaf(a[i], b[j], sreg[i][j]);
        }

        if (kt == qi) {
#pragma unroll
            for (int i = 0; i < 4; i++)
#pragma unroll
                for (int j = 0; j < 4; j++)
                    if (k0 + tx*4 + j > q0 + ty*4 + i) sreg[i][j] = NEG_BIG;
        }

        float p[4][4];
#pragma unroll
        for (int i = 0; i < 4; i++) {
            float mt = fmaxf(fmaxf(sreg[i][0], sreg[i][1]),
                             fmaxf(sreg[i][2], sreg[i][3]));
#pragma unroll
            for (int off = 1; off < 16; off <<= 1)
                mt = fmaxf(mt, __shfl_xor_sync(0xffffffffu, mt, off));
            float mn   = fmaxf(m_i[i], mt);
            float corr = __expf(m_i[i] - mn);
            m_i[i] = mn;
            float ls = 0.f;
#pragma unroll
            for (int j = 0; j < 4; j++) {
                float pv = __expf(sreg[i][j] - mn);
                p[i][j] = pv;
                ls += pv;
            }
#pragma unroll
            for (int off = 1; off < 16; off <<= 1)
                ls += __shfl_xor_sync(0xffffffffu, ls, off);
            l_i[i] = l_i[i]*corr + ls;
#pragma unroll
            for (int j = 0; j < 8; j++) acc[i][j] *= corr;
        }

#pragma unroll
        for (int i = 0; i < 4; i++)
            *(float4*)&Ps[(ty*4 + i)*68 + tx*4] = *(float4*)&p[i][0];
        __syncthreads();

        for (int k = 0; k < 64; k++) {
            float av[4];
            av[0] = Ps[(ty*4 + 0)*68 + k];
            av[1] = Ps[(ty*4 + 1)*68 + k];
            av[2] = Ps[(ty*4 + 2)*68 + k];
            av[3] = Ps[(ty*4 + 3)*68 + k];
            float4 b0 = *(const float4*)&Vs[k*128 + tx*8];
            float4 b1 = *(const float4*)&Vs[k*128 + tx*8 + 4];
            float bv[8] = {b0.x, b0.y, b0.z, b0.w, b1.x, b1.y, b1.z, b1.w};
#pragma unroll
            for (int i = 0; i < 4; i++)
#pragma unroll
                for (int j = 0; j < 8; j++)
                    acc[i][j] = fmaf(av[i], bv[j], acc[i][j]);
        }
    }

    int bb = bh >> 4, h = bh & 15;
#pragma unroll
    for (int i = 0; i < 4; i++) {
        float inv = 1.0f / l_i[i];
        int srow = q0 + ty*4 + i;
        float* op = g_o + ((size_t)bb*NS + srow)*ND + h*HD + tx*8;
#pragma unroll
        for (int j = 0; j < 8; j++) op[j] = acc[i][j] * inv;
    }
}

// ---------------------------------------------------------------------------
extern "C" void kernel_launch(void* const* d_in, const int* in_sizes, int n_in,
                              void* d_out, int out_size) {
    const float* x  = (const float*)d_in[0];
    const float* wq = (const float*)d_in[1];
    const float* wk = (const float*)d_in[2];
    const float* wv = (const float*)d_in[3];
    const float* wo = (const float*)d_in[4];
    // d_in[5] = attn_mask (known causal tril; handled analytically)
    float* out = (float*)d_out;

    __nv_bfloat16 *px2, *po2, *pwq2, *pwk2, *pwv2, *pwo2;
    cudaGetSymbolAddress((void**)&px2,  gx2);
    cudaGetSymbolAddress((void**)&po2,  go2);
    cudaGetSymbolAddress((void**)&pwq2, gwq2);
    cudaGetSymbolAddress((void**)&pwk2, gwk2);
    cudaGetSymbolAddress((void**)&pwv2, gwv2);
    cudaGetSymbolAddress((void**)&pwo2, gwo2);

    rope_init_kernel<<<NS, 64>>>();

    conv_split<0><<<(NM*ND)/256, 256>>>(x,  px2);
    conv_split<1><<<(ND*ND)/256, 256>>>(wq, pwq2);
    conv_split<1><<<(ND*ND)/256, 256>>>(wk, pwk2);
    conv_split<1><<<(ND*ND)/256, 256>>>(wv, pwv2);
    conv_split<1><<<(ND*ND)/256, 256>>>(wo, pwo2);

    dim3 gg(ND/128, NM/128);   // (16, 32)
    hgemm_nt<0><<<gg, 256>>>(px2, pwq2, nullptr);
    hgemm_nt<1><<<gg, 256>>>(px2, pwk2, nullptr);
    hgemm_nt<2><<<gg, 256>>>(px2, pwv2, nullptr);

    size_t smem = (size_t)(128*64*2 + 64*128 + 64*68) * sizeof(float); // 115712 B
    cudaFuncSetAttribute(flash_attn, cudaFuncAttributeMaxDynamicSharedMemorySize,
                         (int)smem);
    flash_attn<<<dim3(NS/64, NB*NH), 256, smem>>>();

    float* po_f32;
    cudaGetSymbolAddress((void**)&po_f32, g_o);
    conv_split<0><<<(NM*ND)/256, 256>>>(po_f32, po2);
    hgemm_nt<3><<<gg, 256>>>(po2, pwo2, out);
}

// round 15
// speedup vs baseline: 1.2227x; 1.2227x over previous
#include <cuda_runtime.h>
#include <cuda_bf16.h>
#include <math.h>
#include <float.h>
#include <stdint.h>

// Problem constants
#define NB 2
#define NS 2048
#define ND 2048
#define NH 16
#define HD 128
#define NM (NB*NS)          // 4096 rows for GEMMs
#define K2 (3*ND)           // 6144: split-bf16 K concat [hi|lo|hi] x [hi|hi|lo]
#define D2 384              // split headdim (flash S gemm)
#define BC2 192             // split Bc (flash PV gemm)
#define NEG_BIG (-3.402823466e38f)
#define SCALE_F 0.08838834764831845f   // 1/sqrt(128)

// Scratch (allocations banned -> device globals)
__device__ float g_v[NB*NH*NS*HD];          // fp32 V [bh][s][d] (for transpose)
__device__ float g_o[NB*NS*ND];             // attention out [b][s][h*hd+d]
__device__ float g_cos[NS*(HD/2)];
__device__ float g_sin[NS*(HD/2)];
__device__ __nv_bfloat16 gx2 [NM*K2];       // split(x)   [hi|lo|hi]
__device__ __nv_bfloat16 go2 [NM*K2];       // split(g_o) [hi|lo|hi]
__device__ __nv_bfloat16 gwq2[ND*K2];       // split(w)   [hi|hi|lo]
__device__ __nv_bfloat16 gwk2[ND*K2];
__device__ __nv_bfloat16 gwv2[ND*K2];
__device__ __nv_bfloat16 gwo2[ND*K2];
__device__ __nv_bfloat16 g_q2[NB*NH*NS*D2];      // rope'd+scaled Q split [hi|lo|hi] along d
__device__ __nv_bfloat16 g_k2[NB*NH*NS*D2];      // rope'd K split [hi|hi|lo] along d
__device__ __nv_bfloat16 g_v2t[NB*NH*HD*(3*NS)]; // V^T split [hi|hi|lo] along s

// ---------------------------------------------------------------------------
// RoPE tables (reference strided-slice semantics)
// ---------------------------------------------------------------------------
__global__ void rope_init_kernel() {
    int s = blockIdx.x;
    int i = threadIdx.x;            // 0..63
    int fc = (2*i) & 63;
    int fs = (2*i + 1) & 63;
    double invc = pow(10000.0, -(double)(2*fc) / 128.0);
    double invs = pow(10000.0, -(double)(2*fs) / 128.0);
    g_cos[s*64 + i] = (float)cos((double)s * invc);
    g_sin[s*64 + i] = (float)sin((double)s * invs);
}

// ---------------------------------------------------------------------------
// fp32 -> split bf16 (hi+lo). PAT 0: [hi,lo,hi]. PAT 1: [hi,hi,lo].
// ---------------------------------------------------------------------------
template<int PAT>
__global__ void conv_split(const float* __restrict__ src,
                           __nv_bfloat16* __restrict__ dst) {
    int idx = blockIdx.x * 256 + threadIdx.x;
    float v = src[idx];
    __nv_bfloat16 hi = __float2bfloat16(v);
    __nv_bfloat16 lo = __float2bfloat16(v - __bfloat162float(hi));
    int row = idx >> 11;
    int k   = idx & 2047;
    size_t base = (size_t)row * K2 + k;
    if (PAT == 0) {
        dst[base] = hi; dst[base + ND] = lo; dst[base + 2*ND] = hi;
    } else {
        dst[base] = hi; dst[base + ND] = hi; dst[base + 2*ND] = lo;
    }
}

// ---------------------------------------------------------------------------
// mma.sync m16n8k16 row.col bf16 -> f32 (fragment layout HW-verified R10)
// ---------------------------------------------------------------------------
__device__ __forceinline__ void mma_bf16(float* c, const uint32_t* a, const uint32_t* b) {
    asm volatile(
        "mma.sync.aligned.m16n8k16.row.col.f32.bf16.bf16.f32 "
        "{%0,%1,%2,%3}, {%4,%5,%6,%7}, {%8,%9}, {%0,%1,%2,%3};\n"
        : "+f"(c[0]), "+f"(c[1]), "+f"(c[2]), "+f"(c[3])
        : "r"(a[0]), "r"(a[1]), "r"(a[2]), "r"(a[3]), "r"(b[0]), "r"(b[1]));
}

__device__ __forceinline__ uint32_t cvta_smem(const void* p) {
    uint32_t a;
    asm("{ .reg .u64 t; cvta.to.shared.u64 t, %1; cvt.u32.u64 %0, t; }"
        : "=r"(a) : "l"(p));
    return a;
}
__device__ __forceinline__ void ldsm_x4(uint32_t& r0, uint32_t& r1,
                                        uint32_t& r2, uint32_t& r3, uint32_t a) {
    asm volatile("ldmatrix.sync.aligned.m8n8.x4.shared.b16 {%0,%1,%2,%3}, [%4];"
                 : "=r"(r0), "=r"(r1), "=r"(r2), "=r"(r3) : "r"(a));
}

// ---------------------------------------------------------------------------
// NT bf16 GEMM (tensor cores), K2=6144. Unchanged verified mainloop.
// MODE 0: -> g_q2 (RoPE+scale, split) 1: -> g_k2 (RoPE, split)
// MODE 2: -> g_v fp32 (head layout)   3: -> outp row-major
// ---------------------------------------------------------------------------
template<int MODE>
__global__ __launch_bounds__(256) void hgemm_nt(const __nv_bfloat16* __restrict__ A2,
                                                const __nv_bfloat16* __restrict__ B2,
                                                float* __restrict__ outp) {
    __shared__ __nv_bfloat16 As[2][128*40];
    __shared__ __nv_bfloat16 Bs[2][128*40];
    const int t    = threadIdx.x;
    const int warp = t >> 5;
    const int lane = t & 31;
    const int g    = lane >> 2;
    const int tg   = lane & 3;
    const int wm   = (warp >> 2) * 64;
    const int wn   = (warp & 3) * 32;
    const int m0   = blockIdx.y * 128;
    const int n0   = blockIdx.x * 128;

    float c[4][4][4];
#pragma unroll
    for (int mf = 0; mf < 4; mf++)
#pragma unroll
        for (int nf = 0; nf < 4; nf++)
#pragma unroll
            for (int r = 0; r < 4; r++) c[mf][nf][r] = 0.f;

    const int lr = t >> 1;
    const int lc = (t & 1) * 16;
    const __nv_bfloat16* Ap = A2 + (size_t)(m0 + lr) * K2 + lc;
    const __nv_bfloat16* Bp = B2 + (size_t)(n0 + lr) * K2 + lc;

    {
        uint4 a0 = *(const uint4*)(Ap);
        uint4 a1 = *(const uint4*)(Ap + 8);
        uint4 b0 = *(const uint4*)(Bp);
        uint4 b1 = *(const uint4*)(Bp + 8);
        *(uint4*)&As[0][lr*40 + lc]     = a0;
        *(uint4*)&As[0][lr*40 + lc + 8] = a1;
        *(uint4*)&Bs[0][lr*40 + lc]     = b0;
        *(uint4*)&Bs[0][lr*40 + lc + 8] = b1;
    }
    __syncthreads();

    int buf = 0;
    for (int k0 = 0; k0 < K2; k0 += 32) {
        uint4 na0, na1, nb0, nb1;
        const bool has_next = (k0 + 32) < K2;
        if (has_next) {
            na0 = *(const uint4*)(Ap + k0 + 32);
            na1 = *(const uint4*)(Ap + k0 + 40);
            nb0 = *(const uint4*)(Bp + k0 + 32);
            nb1 = *(const uint4*)(Bp + k0 + 40);
        }
        const __nv_bfloat16* Asb = &As[buf][0];
        const __nv_bfloat16* Bsb = &Bs[buf][0];
#pragma unroll
        for (int ks = 0; ks < 2; ks++) {
            uint32_t af[4][4];
#pragma unroll
            for (int mf = 0; mf < 4; mf++) {
                int r0 = (wm + mf*16 + g)*40 + ks*16 + tg*2;
                af[mf][0] = *(const uint32_t*)&Asb[r0];
                af[mf][1] = *(const uint32_t*)&Asb[r0 + 8*40];
                af[mf][2] = *(const uint32_t*)&Asb[r0 + 8];
                af[mf][3] = *(const uint32_t*)&Asb[r0 + 8*40 + 8];
            }
            uint32_t bfr[4][2];
#pragma unroll
            for (int nf = 0; nf < 4; nf++) {
                int r0 = (wn + nf*8 + g)*40 + ks*16 + tg*2;
                bfr[nf][0] = *(const uint32_t*)&Bsb[r0];
                bfr[nf][1] = *(const uint32_t*)&Bsb[r0 + 8];
            }
#pragma unroll
            for (int mf = 0; mf < 4; mf++)
#pragma unroll
                for (int nf = 0; nf < 4; nf++)
                    mma_bf16(c[mf][nf], af[mf], bfr[nf]);
        }
        if (has_next) {
            int nb = buf ^ 1;
            *(uint4*)&As[nb][lr*40 + lc]     = na0;
            *(uint4*)&As[nb][lr*40 + lc + 8] = na1;
            *(uint4*)&Bs[nb][lr*40 + lc]     = nb0;
            *(uint4*)&Bs[nb][lr*40 + lc + 8] = nb1;
            __syncthreads();
            buf = nb;
        }
    }

    // Epilogue: frag (mf,nf) reg r -> row m0+wm+mf*16+g+(r>=2)*8,
    // col n0+wn+nf*8+tg*2+(r&1). Col pairs (even,odd) intra-thread.
#pragma unroll
    for (int mf = 0; mf < 4; mf++) {
#pragma unroll
        for (int nf = 0; nf < 4; nf++) {
            int col = n0 + wn + nf*8 + tg*2;
#pragma unroll
            for (int rp = 0; rp < 2; rp++) {
                int row = m0 + wm + mf*16 + g + rp*8;
                float ve = c[mf][nf][rp*2];
                float vo = c[mf][nf][rp*2 + 1];
                int bb = row >> 11;
                int ss = row & 2047;
                if (MODE == 3) {
                    float2 p; p.x = ve; p.y = vo;
                    *(float2*)&outp[(size_t)row * ND + col] = p;
                } else if (MODE == 2) {
                    int h = col >> 7, d = col & 127;
                    size_t base = (((size_t)(bb*NH + h))*NS + ss)*HD + d;
                    g_v[base]     = ve;
                    g_v[base + 1] = vo;
                } else {
                    int h = col >> 7, d = col & 127;
                    int ip = d >> 1;
                    float cc = g_cos[ss*64 + ip];
                    float sn = g_sin[ss*64 + ip];
                    float re = ve*cc - vo*sn;
                    float ro = ve*sn + vo*cc;
                    if (MODE == 0) { re *= SCALE_F; ro *= SCALE_F; }
                    __nv_bfloat16 he = __float2bfloat16(re);
                    __nv_bfloat16 ho = __float2bfloat16(ro);
                    __nv_bfloat16 le = __float2bfloat16(re - __bfloat162float(he));
                    __nv_bfloat16 lo2 = __float2bfloat16(ro - __bfloat162float(ho));
                    size_t qb = ((size_t)(bb*NH + h)*NS + ss)*D2 + d;
                    if (MODE == 0) {           // Q: [hi|lo|hi]
                        g_q2[qb]     = he; g_q2[qb+1]   = ho;
                        g_q2[qb+128] = le; g_q2[qb+129] = lo2;
                        g_q2[qb+256] = he; g_q2[qb+257] = ho;
                    } else {                   // K: [hi|hi|lo]
                        g_k2[qb]     = he; g_k2[qb+1]   = ho;
                        g_k2[qb+128] = he; g_k2[qb+129] = ho;
                        g_k2[qb+256] = le; g_k2[qb+257] = lo2;
                    }
                }
            }
        }
    }
}

// ---------------------------------------------------------------------------
// V fp32 [bh][s][d] -> V^T split bf16 [bh][d][seg*2048+s], segs [hi|hi|lo]
// ---------------------------------------------------------------------------
__global__ __launch_bounds__(256) void v_transpose_split() {
    __shared__ float ts[64][133];
    int bh = blockIdx.y, s0 = blockIdx.x * 64;
    const float* src = g_v + ((size_t)bh*NS + s0)*HD;
    for (int idx = threadIdx.x; idx < 64*32; idx += 256) {
        int r = idx >> 5, cc = (idx & 31) << 2;
        float4 v = *(const float4*)&src[r*HD + cc];
        ts[r][cc] = v.x; ts[r][cc+1] = v.y; ts[r][cc+2] = v.z; ts[r][cc+3] = v.w;
    }
    __syncthreads();
    __nv_bfloat16* dst = g_v2t + (size_t)bh * HD * (3*NS);
    for (int it = 0; it < 32; it++) {
        int idx = threadIdx.x + it*256;
        int d = idx >> 6, j = idx & 63;
        float v = ts[j][d];
        __nv_bfloat16 hi = __float2bfloat16(v);
        __nv_bfloat16 lo = __float2bfloat16(v - __bfloat162float(hi));
        size_t o = (size_t)d*(3*NS) + s0 + j;
        dst[o] = hi; dst[o + NS] = hi; dst[o + 2*NS] = lo;
    }
}

// ---------------------------------------------------------------------------
// Flash attention on tensor cores. 64 q-rows per CTA, Bc=64, causal.
// S over k=D2 (24 mma steps), PV over k=BC2 (12 steps). 8 warps (4x2).
// ---------------------------------------------------------------------------
#define QP 392   // Q/K smem pitch (halves); 784B == 16 mod 128 -> ldsm conflict-free
#define VP 200   // V^T pitch; 400B == 16 mod 128
#define PP 200   // P pitch

__global__ __launch_bounds__(256) void flash_mma() {
    extern __shared__ __nv_bfloat16 sb[];
    __nv_bfloat16* Qs = sb;                   // [64][QP]
    __nv_bfloat16* Ks = sb + 64*QP;           // [64][QP]
    __nv_bfloat16* Vs = sb + 2*64*QP;         // [128][VP]
    __nv_bfloat16* Ps = Vs + 128*VP;          // [64][PP]
    float* redm = (float*)(Ps + 64*PP);       // [2][64]
    float* redl = redm + 128;                 // [2][64]

    const int t = threadIdx.x;
    const int lane = t & 31;
    const int warp = t >> 5;
    const int g  = lane >> 2;
    const int tg = lane & 3;
    const int wrow = warp >> 1;   // 0..3 -> 16 q-rows
    const int wcol = warp & 1;    // 0..1 -> 32 S-cols / 64 O-cols
    const int qi = blockIdx.x;
    const int bh = blockIdx.y;
    const int q0 = qi * 64;

    const __nv_bfloat16* Qg = g_q2 + (size_t)bh * NS * D2;
    const __nv_bfloat16* Kg = g_k2 + (size_t)bh * NS * D2;
    const __nv_bfloat16* Vg = g_v2t + (size_t)bh * HD * (3*NS);

    // Load Q tile once (64 rows x 384 halves)
    for (int idx = t; idx < 64*48; idx += 256) {
        int r = idx / 48, cc = (idx % 48) * 8;
        *(uint4*)&Qs[r*QP + cc] = *(const uint4*)&Qg[(size_t)(q0 + r)*D2 + cc];
    }

    float m_i[2] = {NEG_BIG, NEG_BIG};
    float l_i[2] = {0.f, 0.f};
    float acc[8][4];
#pragma unroll
    for (int nf = 0; nf < 8; nf++)
#pragma unroll
        for (int r = 0; r < 4; r++) acc[nf][r] = 0.f;

    const uint32_t qs_b = cvta_smem(Qs);
    const uint32_t ks_b = cvta_smem(Ks);
    const uint32_t vs_b = cvta_smem(Vs);
    const uint32_t ps_b = cvta_smem(Ps);
    // ldmatrix lane-address components:
    //  A (16x16): lanes 0-7 rows 0-7/k0, 8-15 rows 8-15/k0, 16-23 rows 0-7/k8, 24-31 rows 8-15/k8
    const int a_row = lane & 15;
    const int a_c8  = (lane >> 4) * 8;
    //  B (two 8x16 n-frags): lanes 0-7 rows 0-7/k0, 8-15 rows 0-7/k8,
    //                        16-23 rows 8-15/k0, 24-31 rows 8-15/k8
    const int b_row = (lane & 7) + ((lane >> 4) << 3);
    const int b_c8  = ((lane >> 3) & 1) * 8;

    const int ntiles = qi + 1;
    for (int kt = 0; kt < ntiles; kt++) {
        const int k0 = kt * 64;
        __syncthreads();   // prev PV done with Ps/Vs/Ks
        for (int idx = t; idx < 64*48; idx += 256) {
            int r = idx / 48, cc = (idx % 48) * 8;
            *(uint4*)&Ks[r*QP + cc] = *(const uint4*)&Kg[(size_t)(k0 + r)*D2 + cc];
        }
        for (int idx = t; idx < 128*24; idx += 256) {
            int d = idx / 24, c8 = idx % 24;
            int seg = c8 >> 3, j8 = (c8 & 7) * 8;
            *(uint4*)&Vs[d*VP + c8*8] =
                *(const uint4*)&Vg[(size_t)d*(3*NS) + (size_t)seg*NS + k0 + j8];
        }
        __syncthreads();

        // S = Q K^T  (split precision baked into data)
        float sc[4][4];
#pragma unroll
        for (int nf = 0; nf < 4; nf++)
#pragma unroll
            for (int r = 0; r < 4; r++) sc[nf][r] = 0.f;

#pragma unroll
        for (int ks = 0; ks < 24; ks++) {
            uint32_t a0,a1,a2,a3;
            ldsm_x4(a0,a1,a2,a3,
                    qs_b + (uint32_t)(((wrow*16 + a_row)*QP + ks*16 + a_c8) * 2));
            uint32_t af[4] = {a0,a1,a2,a3};
            uint32_t bfr[4][2];
#pragma unroll
            for (int p = 0; p < 2; p++) {
                uint32_t b0,b1,b2,b3;
                ldsm_x4(b0,b1,b2,b3,
                        ks_b + (uint32_t)(((wcol*32 + p*16 + b_row)*QP + ks*16 + b_c8) * 2));
                bfr[2*p][0]=b0; bfr[2*p][1]=b1; bfr[2*p+1][0]=b2; bfr[2*p+1][1]=b3;
            }
#pragma unroll
            for (int nf = 0; nf < 4; nf++) mma_bf16(sc[nf], af, bfr[nf]);
        }

        // Causal mask on the diagonal tile (q0 == k0)
        if (kt == qi) {
#pragma unroll
            for (int nf = 0; nf < 4; nf++)
#pragma unroll
                for (int r = 0; r < 4; r++) {
                    int row = wrow*16 + g + (r >> 1)*8;
                    int col = wcol*32 + nf*8 + tg*2 + (r & 1);
                    if (col > row) sc[nf][r] = NEG_BIG;
                }
        }

        // Online softmax: warp-partial (32 cols) then 2-warp smem exchange
        float pm[2], corr[2], psum[2];
#pragma unroll
        for (int rp = 0; rp < 2; rp++) {
            float m = NEG_BIG;
#pragma unroll
            for (int nf = 0; nf < 4; nf++)
                m = fmaxf(m, fmaxf(sc[nf][rp*2], sc[nf][rp*2+1]));
            m = fmaxf(m, __shfl_xor_sync(0xffffffffu, m, 1));
            m = fmaxf(m, __shfl_xor_sync(0xffffffffu, m, 2));
            pm[rp] = m;
            int r = wrow*16 + g + rp*8;
            if (tg == 0) redm[wcol*64 + r] = m;
        }
        __syncthreads();
#pragma unroll
        for (int rp = 0; rp < 2; rp++) {
            int r = wrow*16 + g + rp*8;
            float tm = fmaxf(pm[rp], redm[(wcol^1)*64 + r]);
            float mn = fmaxf(m_i[rp], tm);
            corr[rp] = __expf(m_i[rp] - mn);
            m_i[rp] = mn;
            float s = 0.f;
#pragma unroll
            for (int nf = 0; nf < 4; nf++)
#pragma unroll
                for (int j = 0; j < 2; j++) {
                    float pv = __expf(sc[nf][rp*2+j] - mn);
                    sc[nf][rp*2+j] = pv;
                    s += pv;
                }
            s += __shfl_xor_sync(0xffffffffu, s, 1);
            s += __shfl_xor_sync(0xffffffffu, s, 2);
            psum[rp] = s;
            if (tg == 0) redl[wcol*64 + r] = s;
        }
        // Write P split [hi|lo|hi] along k to Ps
#pragma unroll
        for (int nf = 0; nf < 4; nf++)
#pragma unroll
            for (int r = 0; r < 4; r++) {
                int row = wrow*16 + g + (r >> 1)*8;
                int col = wcol*32 + nf*8 + tg*2 + (r & 1);
                float pv = sc[nf][r];
                __nv_bfloat16 hi = __float2bfloat16(pv);
                __nv_bfloat16 lo = __float2bfloat16(pv - __bfloat162float(hi));
                Ps[row*PP + col]       = hi;
                Ps[row*PP + 64 + col]  = lo;
                Ps[row*PP + 128 + col] = hi;
            }
        __syncthreads();
#pragma unroll
        for (int rp = 0; rp < 2; rp++) {
            int r = wrow*16 + g + rp*8;
            float tsum = psum[rp] + redl[(wcol^1)*64 + r];
            l_i[rp] = l_i[rp]*corr[rp] + tsum;
#pragma unroll
            for (int nf = 0; nf < 8; nf++) {
                acc[nf][rp*2]   *= corr[rp];
                acc[nf][rp*2+1] *= corr[rp];
            }
        }

        // O += P V  (A=Ps [64][192], B=Vs rows=d [128][192])
#pragma unroll
        for (int ks = 0; ks < 12; ks++) {
            uint32_t a0,a1,a2,a3;
            ldsm_x4(a0,a1,a2,a3,
                    ps_b + (uint32_t)(((wrow*16 + a_row)*PP + ks*16 + a_c8) * 2));
            uint32_t af[4] = {a0,a1,a2,a3};
#pragma unroll
            for (int p = 0; p < 4; p++) {
                uint32_t b0,b1,b2,b3;
                ldsm_x4(b0,b1,b2,b3,
                        vs_b + (uint32_t)(((wcol*64 + p*16 + b_row)*VP + ks*16 + b_c8) * 2));
                uint32_t bA[2] = {b0,b1}, bB[2] = {b2,b3};
                mma_bf16(acc[2*p],   af, bA);
                mma_bf16(acc[2*p+1], af, bB);
            }
        }
    }

    // Finalize
    const int bb = bh >> 4, h = bh & 15;
#pragma unroll
    for (int rp = 0; rp < 2; rp++) {
        float inv = 1.0f / l_i[rp];
        int srow = q0 + wrow*16 + g + rp*8;
        float* op = g_o + ((size_t)bb*NS + srow)*ND + h*HD;
#pragma unroll
        for (int nf = 0; nf < 8; nf++) {
            int col = wcol*64 + nf*8 + tg*2;
            float2 v2;
            v2.x = acc[nf][rp*2]   * inv;
            v2.y = acc[nf][rp*2+1] * inv;
            *(float2*)&op[col] = v2;
        }
    }
}

// ---------------------------------------------------------------------------
extern "C" void kernel_launch(void* const* d_in, const int* in_sizes, int n_in,
                              void* d_out, int out_size) {
    const float* x  = (const float*)d_in[0];
    const float* wq = (const float*)d_in[1];
    const float* wk = (const float*)d_in[2];
    const float* wv = (const float*)d_in[3];
    const float* wo = (const float*)d_in[4];
    float* out = (float*)d_out;

    __nv_bfloat16 *px2, *po2, *pwq2, *pwk2, *pwv2, *pwo2;
    cudaGetSymbolAddress((void**)&px2,  gx2);
    cudaGetSymbolAddress((void**)&po2,  go2);
    cudaGetSymbolAddress((void**)&pwq2, gwq2);
    cudaGetSymbolAddress((void**)&pwk2, gwk2);
    cudaGetSymbolAddress((void**)&pwv2, gwv2);
    cudaGetSymbolAddress((void**)&pwo2, gwo2);

    rope_init_kernel<<<NS, 64>>>();

    conv_split<0><<<(NM*ND)/256, 256>>>(x,  px2);
    conv_split<1><<<(ND*ND)/256, 256>>>(wq, pwq2);
    conv_split<1><<<(ND*ND)/256, 256>>>(wk, pwk2);
    conv_split<1><<<(ND*ND)/256, 256>>>(wv, pwv2);
    conv_split<1><<<(ND*ND)/256, 256>>>(wo, pwo2);

    dim3 gg(ND/128, NM/128);   // (16, 32)
    hgemm_nt<0><<<gg, 256>>>(px2, pwq2, nullptr);
    hgemm_nt<1><<<gg, 256>>>(px2, pwk2, nullptr);
    hgemm_nt<2><<<gg, 256>>>(px2, pwv2, nullptr);

    v_transpose_split<<<dim3(NS/64, NB*NH), 256>>>();

    size_t fsmem = (size_t)(2*64*QP + 128*VP + 64*PP) * sizeof(__nv_bfloat16) + 1024;
    cudaFuncSetAttribute(flash_mma, cudaFuncAttributeMaxDynamicSharedMemorySize,
                         (int)fsmem);
    flash_mma<<<dim3(NS/64, NB*NH), 256, fsmem>>>();

    float* po_f32;
    cudaGetSymbolAddress((void**)&po_f32, g_o);
    conv_split<0><<<(NM*ND)/256, 256>>>(po_f32, po2);
    hgemm_nt<3><<<gg, 256>>>(po2, pwo2, out);
}